// round 1
// baseline (speedup 1.0000x reference)
#include <cuda_runtime.h>

#define BB 16384
#define TT 64

// Ping-pong layer buffers: [B][T][64] (fwd in [0:32), bwd in [32:64))
__device__ float g_buf0[BB * TT * 64];
__device__ float g_buf1[BB * TT * 64];

__device__ __forceinline__ float sigf(float x) {
    return __fdividef(1.0f, 1.0f + __expf(-x));
}
__device__ __forceinline__ float tanh_fast(float x) {
    float e = __expf(-2.0f * x);
    return __fdividef(1.0f - e, 1.0f + e);
}

// ---------------------------------------------------------------------------
// Layer 0: input K=2. One warp per (batch, dir). Lane j owns hidden unit j,
// computes all 3 gates. Whh rows in registers, h broadcast via smem (double
// buffered, one __syncwarp per step).
// ---------------------------------------------------------------------------
__global__ __launch_bounds__(128) void gru_l0(
    const float* __restrict__ x,
    const float* __restrict__ Wih0, const float* __restrict__ Whh0,
    const float* __restrict__ bih0, const float* __restrict__ bhh0)
{
    const int w = threadIdx.x >> 5, lane = threadIdx.x & 31;
    const int b = blockIdx.x * 4 + w;
    const int dir = blockIdx.y;

    __shared__ float hb[4][2][32];

    const float* wi = Wih0 + dir * 96 * 2;
    const float* wh = Whh0 + dir * 96 * 32;
    const float* bi = bih0 + dir * 96;
    const float* bh = bhh0 + dir * 96;

    const float wx0 = wi[(lane) * 2 + 0],     wx1 = wi[(lane) * 2 + 1];
    const float wz0 = wi[(32 + lane) * 2 + 0], wz1 = wi[(32 + lane) * 2 + 1];
    const float wn0 = wi[(64 + lane) * 2 + 0], wn1 = wi[(64 + lane) * 2 + 1];

    float whr[32], whz[32], whn[32];
#pragma unroll
    for (int k = 0; k < 32; k += 4) {
        float4 a = *(const float4*)&wh[(lane) * 32 + k];
        whr[k] = a.x; whr[k + 1] = a.y; whr[k + 2] = a.z; whr[k + 3] = a.w;
        float4 c = *(const float4*)&wh[(32 + lane) * 32 + k];
        whz[k] = c.x; whz[k + 1] = c.y; whz[k + 2] = c.z; whz[k + 3] = c.w;
        float4 d = *(const float4*)&wh[(64 + lane) * 32 + k];
        whn[k] = d.x; whn[k + 1] = d.y; whn[k + 2] = d.z; whn[k + 3] = d.w;
    }
    const float br  = bi[lane] + bh[lane];
    const float bz  = bi[32 + lane] + bh[32 + lane];
    const float bxn = bi[64 + lane];
    const float bhn = bh[64 + lane];

    float h = 0.0f;
    hb[w][0][lane] = 0.0f;
    __syncwarp();

    const float* xp = x + (size_t)b * TT * 2;
    float* outp = g_buf0 + (size_t)b * TT * 64 + dir * 32 + lane;

    for (int t = 0; t < TT; t++) {
        const int te = dir ? (TT - 1 - t) : t;
        const float x0 = __ldg(&xp[te * 2 + 0]);
        const float x1 = __ldg(&xp[te * 2 + 1]);

        float sr = fmaf(x1, wx1, fmaf(x0, wx0, br));
        float sz = fmaf(x1, wz1, fmaf(x0, wz0, bz));
        float sn = fmaf(x1, wn1, fmaf(x0, wn0, bxn));
        float gh = bhn;

        const float4* h4 = (const float4*)hb[w][t & 1];
#pragma unroll
        for (int c = 0; c < 8; c++) {
            float4 v = h4[c];
            sr = fmaf(v.x, whr[4 * c + 0], sr);
            sr = fmaf(v.y, whr[4 * c + 1], sr);
            sr = fmaf(v.z, whr[4 * c + 2], sr);
            sr = fmaf(v.w, whr[4 * c + 3], sr);
            sz = fmaf(v.x, whz[4 * c + 0], sz);
            sz = fmaf(v.y, whz[4 * c + 1], sz);
            sz = fmaf(v.z, whz[4 * c + 2], sz);
            sz = fmaf(v.w, whz[4 * c + 3], sz);
            gh = fmaf(v.x, whn[4 * c + 0], gh);
            gh = fmaf(v.y, whn[4 * c + 1], gh);
            gh = fmaf(v.z, whn[4 * c + 2], gh);
            gh = fmaf(v.w, whn[4 * c + 3], gh);
        }
        const float r = sigf(sr);
        const float z = sigf(sz);
        const float n = tanh_fast(fmaf(r, gh, sn));
        h = fmaf(z, h - n, n);

        hb[w][(t + 1) & 1][lane] = h;
        outp[(size_t)te * 64] = h;
        __syncwarp();
    }
}

// ---------------------------------------------------------------------------
// Layers 1/2: input K=64. 3 warps per (batch, dir), one gate per warp so all
// weights (64+32 floats) fit in registers. Gate combine through smem; warp 1
// (z-gate) owns the h update and the output store.
//   phase = 0: buf0 -> buf1 (layer 1);  phase = 1: buf1 -> buf0 (layer 2)
// ---------------------------------------------------------------------------
__global__ __launch_bounds__(96) void gru_l12(
    int phase,
    const float* __restrict__ Wih, const float* __restrict__ Whh,
    const float* __restrict__ bih, const float* __restrict__ bhh)
{
    const float* in  = phase ? g_buf1 : g_buf0;
    float*       out = phase ? g_buf0 : g_buf1;

    const int w = threadIdx.x >> 5, lane = threadIdx.x & 31;
    const int b = blockIdx.x, dir = blockIdx.y;
    const int row = w * 32 + lane;

    const float* wi = Wih + ((size_t)phase * 2 + dir) * 96 * 64;
    const float* wh = Whh + ((size_t)phase * 2 + dir) * 96 * 32;
    const float* bi = bih + ((size_t)phase * 2 + dir) * 96;
    const float* bh = bhh + ((size_t)phase * 2 + dir) * 96;

    float wxa[64], wha[32];
#pragma unroll
    for (int k = 0; k < 64; k += 4) {
        float4 v = *(const float4*)&wi[(size_t)row * 64 + k];
        wxa[k] = v.x; wxa[k + 1] = v.y; wxa[k + 2] = v.z; wxa[k + 3] = v.w;
    }
#pragma unroll
    for (int k = 0; k < 32; k += 4) {
        float4 v = *(const float4*)&wh[(size_t)row * 32 + k];
        wha[k] = v.x; wha[k + 1] = v.y; wha[k + 2] = v.z; wha[k + 3] = v.w;
    }
    float bias_x, bias_h;
    if (w == 2) { bias_x = bi[row]; bias_h = bh[row]; }
    else        { bias_x = bi[row] + bh[row]; bias_h = 0.0f; }

    __shared__ float sx[64];
    __shared__ float sh[32];
    __shared__ float s_r[32];
    __shared__ float s_xn[32];
    __shared__ float s_hn[32];

    const float* inb = in + (size_t)b * TT * 64;
    if (w == 1) sh[lane] = 0.0f;
    {
        const int te0 = dir ? (TT - 1) : 0;
        if (w == 0) sx[lane]      = inb[(size_t)te0 * 64 + lane];
        if (w == 2) sx[32 + lane] = inb[(size_t)te0 * 64 + 32 + lane];
    }
    __syncthreads();

    float h = 0.0f;  // tracked by warp 1
    float* outb = out + (size_t)b * TT * 64 + dir * 32;

    for (int t = 0; t < TT; t++) {
        const int te = dir ? (TT - 1 - t) : t;

        // Prefetch next input row into registers (warps 0 and 2).
        float xpref = 0.0f;
        if (t + 1 < TT && w != 1) {
            const int ten = dir ? (TT - 2 - t) : (t + 1);
            xpref = inb[(size_t)ten * 64 + (w == 0 ? 0 : 32) + lane];
        }

        // Input-gate GEMV: 64 MACs, 4 partial accumulators for ILP.
        float a0 = 0.f, a1 = 0.f, a2 = 0.f, a3 = 0.f;
        const float4* x4 = (const float4*)sx;
#pragma unroll
        for (int c = 0; c < 16; c++) {
            float4 v = x4[c];
            a0 = fmaf(v.x, wxa[4 * c + 0], a0);
            a1 = fmaf(v.y, wxa[4 * c + 1], a1);
            a2 = fmaf(v.z, wxa[4 * c + 2], a2);
            a3 = fmaf(v.w, wxa[4 * c + 3], a3);
        }
        // Recurrent GEMV: 32 MACs.
        float c0 = 0.f, c1 = 0.f, c2 = 0.f, c3 = 0.f;
        const float4* h4 = (const float4*)sh;
#pragma unroll
        for (int c = 0; c < 8; c++) {
            float4 v = h4[c];
            c0 = fmaf(v.x, wha[4 * c + 0], c0);
            c1 = fmaf(v.y, wha[4 * c + 1], c1);
            c2 = fmaf(v.z, wha[4 * c + 2], c2);
            c3 = fmaf(v.w, wha[4 * c + 3], c3);
        }
        const float accx = (a0 + a1) + (a2 + a3) + bias_x;
        const float acch = (c0 + c1) + (c2 + c3) + bias_h;

        float z = 0.0f;
        if (w == 0) {
            s_r[lane] = sigf(accx + acch);
        } else if (w == 1) {
            z = sigf(accx + acch);
        } else {
            s_xn[lane] = accx;
            s_hn[lane] = acch;
        }
        __syncthreads();

        if (w == 1) {
            const float n = tanh_fast(fmaf(s_r[lane], s_hn[lane], s_xn[lane]));
            const float h2 = fmaf(z, h - n, n);
            h = h2;
            sh[lane] = h2;
            outb[(size_t)te * 64 + lane] = h2;
        } else if (t + 1 < TT) {
            sx[(w == 0 ? 0 : 32) + lane] = xpref;
        }
        __syncthreads();
    }
}

// ---------------------------------------------------------------------------
// Final FC: y = tanh(out @ Wfc.T + bfc). Warp per row, shuffle reduction.
// ---------------------------------------------------------------------------
__global__ __launch_bounds__(256) void fc_kernel(
    const float* __restrict__ Wfc, const float* __restrict__ bfc,
    float* __restrict__ outp)
{
    const float* in = g_buf0;  // layer 2 output
    const int lane = threadIdx.x & 31;
    const int warp = (blockIdx.x * blockDim.x + threadIdx.x) >> 5;
    const int nwarps = (gridDim.x * blockDim.x) >> 5;

    const float w0a = __ldg(&Wfc[2 * lane]),      w0b = __ldg(&Wfc[2 * lane + 1]);
    const float w1a = __ldg(&Wfc[64 + 2 * lane]), w1b = __ldg(&Wfc[64 + 2 * lane + 1]);
    const float b0 = __ldg(&bfc[0]), b1 = __ldg(&bfc[1]);

    const int nrows = BB * TT;
    for (int row = warp; row < nrows; row += nwarps) {
        float2 xv = *(const float2*)&in[(size_t)row * 64 + 2 * lane];
        float y0 = fmaf(xv.y, w0b, xv.x * w0a);
        float y1 = fmaf(xv.y, w1b, xv.x * w1a);
#pragma unroll
        for (int o = 16; o > 0; o >>= 1) {
            y0 += __shfl_xor_sync(0xFFFFFFFFu, y0, o);
            y1 += __shfl_xor_sync(0xFFFFFFFFu, y1, o);
        }
        if (lane == 0) {
            float2 r;
            r.x = tanh_fast(y0 + b0);
            r.y = tanh_fast(y1 + b1);
            *(float2*)&outp[(size_t)row * 2] = r;
        }
    }
}

// ---------------------------------------------------------------------------
extern "C" void kernel_launch(void* const* d_in, const int* in_sizes, int n_in,
                              void* d_out, int out_size)
{
    const float* x    = (const float*)d_in[0];
    const float* Wih0 = (const float*)d_in[1];
    const float* Whh0 = (const float*)d_in[2];
    const float* bih0 = (const float*)d_in[3];
    const float* bhh0 = (const float*)d_in[4];
    const float* Wih  = (const float*)d_in[5];
    const float* Whh  = (const float*)d_in[6];
    const float* bih  = (const float*)d_in[7];
    const float* bhh  = (const float*)d_in[8];
    const float* Wfc  = (const float*)d_in[9];
    const float* bfc  = (const float*)d_in[10];
    float* out = (float*)d_out;

    gru_l0<<<dim3(BB / 4, 2), 128>>>(x, Wih0, Whh0, bih0, bhh0);
    gru_l12<<<dim3(BB, 2), 96>>>(0, Wih, Whh, bih, bhh);
    gru_l12<<<dim3(BB, 2), 96>>>(1, Wih, Whh, bih, bhh);
    fc_kernel<<<2048, 256>>>(Wfc, bfc, out);
}